// round 13
// baseline (speedup 1.0000x reference)
#include <cuda_runtime.h>
#include <cuda_fp16.h>
#include <cstdint>
#include <math.h>

#define NN   100000
#define EE   1600000
#define ENC  128
#define PI_  98
#define KIN  226          // ENC + PI
#define KCH  240          // KIN padded to multiple of 16
#define MH   512          // 4 stacked [*,128] outputs
#define EMB  128
#define NB_SCAN 98        // ceil(NN/1024)

// ---------------- scratch (static device globals; no allocation) ----------------
__device__ __half   g_wh1[MH * KCH];             // stage-1 fused weights fp16 (rows permuted)
__device__ __half   g_wh2[MH * ENC];             // stage-2 stacked weights fp16 (rows permuted)
__device__ __half   g_xmh[(size_t)NN * ENC];     // stage-1 result fp16
__device__ __align__(16) __half2 g_hh[(size_t)NN * (MH/2)];  // h, interleaved semantics

// CSR (per edge set)
__device__ int     g_cnt   [2][NN];
__device__ int     g_rowptr[2][NN + 1];
__device__ int     g_cur   [2][NN];
__device__ int     g_bsum  [2][NB_SCAN];
__device__ float   g_dis   [2][NN];
__device__ uint2   g_epk   [2][EE];              // {src, half2(dn,einv)}

// inverse interleave map, applied to weight ROWS (see round 10)
__device__ __forceinline__ int inv_feat(int f) {
    int c = f >> 1, t = f & 1;
    int s = c >> 7, q = c & 127;
    int i = ((q >> 2) << 1) | (q & 1);
    int p = (q >> 1) & 1;
    int cb = (s << 7) | (p << 6) | i;
    return (cb << 1) | t;
}

// ---------------- mma helpers ----------------
__device__ __forceinline__ void ldsm4(unsigned &r0, unsigned &r1, unsigned &r2, unsigned &r3,
                                      unsigned addr) {
    asm volatile("ldmatrix.sync.aligned.m8n8.x4.shared.b16 {%0,%1,%2,%3}, [%4];"
                 : "=r"(r0), "=r"(r1), "=r"(r2), "=r"(r3) : "r"(addr));
}
__device__ __forceinline__ void ldsm2(unsigned &r0, unsigned &r1, unsigned addr) {
    asm volatile("ldmatrix.sync.aligned.m8n8.x2.shared.b16 {%0,%1}, [%2];"
                 : "=r"(r0), "=r"(r1) : "r"(addr));
}
__device__ __forceinline__ void mma16816(float &c0, float &c1, float &c2, float &c3,
                                         unsigned a0, unsigned a1, unsigned a2, unsigned a3,
                                         unsigned b0, unsigned b1) {
    asm volatile("mma.sync.aligned.m16n8k16.row.col.f32.f16.f16.f32 "
                 "{%0,%1,%2,%3}, {%4,%5,%6,%7}, {%8,%9}, {%0,%1,%2,%3};"
                 : "+f"(c0), "+f"(c1), "+f"(c2), "+f"(c3)
                 : "r"(a0), "r"(a1), "r"(a2), "r"(a3), "r"(b0), "r"(b1));
}

// ---------------- CSR build ----------------
__global__ void k_zero_cnt() {
    int i = blockIdx.x * blockDim.x + threadIdx.x;
    if (i < NN) { g_cnt[0][i] = 0; g_cnt[1][i] = 0; }
}

__global__ void k_hist(const int* __restrict__ ei0, const int* __restrict__ ei1) {
    int e = blockIdx.x * blockDim.x + threadIdx.x;
    if (e < EE) {
        atomicAdd(&g_cnt[0][ei0[EE + e]], 1);
        atomicAdd(&g_cnt[1][ei1[EE + e]], 1);
    }
}

__global__ void k_scan1() {
    __shared__ int sh[1024];
    int which = blockIdx.y;
    int tid = threadIdx.x;
    int i = blockIdx.x * 1024 + tid;
    int v = (i < NN) ? g_cnt[which][i] : 0;
    sh[tid] = v; __syncthreads();
#pragma unroll
    for (int off = 1; off < 1024; off <<= 1) {
        int t = (tid >= off) ? sh[tid - off] : 0;
        __syncthreads();
        sh[tid] += t;
        __syncthreads();
    }
    if (i < NN) g_rowptr[which][i] = sh[tid] - v;     // exclusive
    if (tid == 1023) g_bsum[which][blockIdx.x] = sh[1023];
}

__global__ void k_scan2() {
    int which = threadIdx.x >> 5;
    if ((threadIdx.x & 31) == 0 && which < 2) {
        int s = 0;
        for (int i = 0; i < NB_SCAN; i++) { int t = g_bsum[which][i]; g_bsum[which][i] = s; s += t; }
    }
}

__global__ void k_scan3() {                           // + dis computation
    int which = blockIdx.y;
    int i = blockIdx.x * blockDim.x + threadIdx.x;
    if (i < NN) {
        int v = g_rowptr[which][i] + g_bsum[which][i >> 10];
        g_rowptr[which][i] = v;
        g_cur[which][i] = v;
        g_dis[which][i] = rsqrtf((float)(g_cnt[which][i] + 1));   // +1 self loop
    }
    if (i == 0) g_rowptr[which][NN] = EE;
}

__global__ void k_fill(const int* __restrict__ ei0, const float* __restrict__ ew0,
                       const int* __restrict__ ei1, const float* __restrict__ ew1) {
    int which = blockIdx.y;
    const int*   ei = which ? ei1 : ei0;
    const float* ew = which ? ew1 : ew0;
    int e = blockIdx.x * blockDim.x + threadIdx.x;
    if (e >= EE) return;
    int r = ei[e];
    int c = ei[EE + e];
    float w = ew[e];
    float dn   = g_dis[which][r] * g_dis[which][c];
    float einv = (w > 0.0f) ? fminf(rsqrtf(w), 1.0f) : 0.0f;
    int p = atomicAdd(&g_cur[which][c], 1);
    __half2 de = __floats2half2_rn(dn, einv);
    uint2 pk;
    pk.x = (unsigned)r;
    pk.y = *(unsigned*)&de;
    g_epk[which][p] = pk;
}

// ---------------- fused weights (rows permuted by inv_feat) ----------------
__global__ void k_build_Wc(const float* __restrict__ W1a, const float* __restrict__ W1b,
                           const float* __restrict__ W2a, const float* __restrict__ W2b,
                           const float* __restrict__ nW1, const float* __restrict__ nW2) {
    int i = blockIdx.x * blockDim.x + threadIdx.x;
    if (i >= MH * KCH) return;
    int m = i / KCH, k = i - m * KCH;
    int mo = inv_feat(m);
    float v = 0.0f;
    if (k < KIN) {
        const float* Ws = (mo < 128) ? W1a : (mo < 256) ? W1b : (mo < 384) ? W2a : W2b;
        const float* nW = (mo < 256) ? nW1 : nW2;
        int mm = mo & 127;
        float s = 0.0f;
#pragma unroll 8
        for (int j = 0; j < ENC; j++) s = fmaf(Ws[mm * ENC + j], nW[j * KIN + k], s);
        v = s;
    }
    g_wh1[i] = __float2half(v);
}

__global__ void k_build_Wc2(const float* __restrict__ W3a, const float* __restrict__ W3b,
                            const float* __restrict__ W4a, const float* __restrict__ W4b) {
    int i = blockIdx.x * blockDim.x + threadIdx.x;
    if (i >= MH * ENC) return;
    int m = i / ENC, k = i - m * ENC;
    int mo = inv_feat(m);
    const float* Ws = (mo < 128) ? W3a : (mo < 256) ? W3b : (mo < 384) ? W4a : W4b;
    g_wh2[i] = __float2half(Ws[(mo & 127) * ENC + k]);
}

// ---------------- persist-A tensor-core GEMM: C[N,512] = A[N,K] * W[512,K]^T ----------------
// stage 0: A = concat(x, d2an) built IN the fill (fp32 -> fp16 in flight)
// stage 1: A = g_xmh (fp16 direct)
__global__ __launch_bounds__(256, 2)
void k_gemm(int stage, const float* __restrict__ x, const float* __restrict__ d2) {
    extern __shared__ __align__(16) __half sm[];
    const __half* __restrict__ W = stage ? g_wh2 : g_wh1;
    const int K  = stage ? ENC : KCH;
    const int SA = K + 8;
    const int nk = K >> 4;

    __half* As = sm;                      // 128 x SA
    __half* Bs = sm + 128 * SA;           // 2 x 128 x 24

    const int tid  = threadIdx.x;
    const int lane = tid & 31;
    const int warp = tid >> 5;
    const int wm   = warp >> 2;
    const int wn   = warp & 3;
    const int bn   = blockIdx.x * 128;

    // ---- fill persistent A ----
    const int rowu4 = K >> 3;             // 30 (stage 0) or 16 (stage 1)
    const int totu4 = 128 * rowu4;
    if (stage == 0) {
        for (int idx = tid; idx < totu4; idx += 256) {
            int r = idx / rowu4;
            int c = idx - r * rowu4;
            int n = bn + r;
            __half h[8];
#pragma unroll
            for (int q = 0; q < 8; q++) h[q] = __float2half(0.0f);
            if (n < NN) {
                int k0 = c * 8;
                if (c < 16) {                       // x region [0,128)
                    float4 a = *(const float4*)(x + (size_t)n * ENC + k0);
                    float4 b = *(const float4*)(x + (size_t)n * ENC + k0 + 4);
                    h[0] = __float2half(a.x); h[1] = __float2half(a.y);
                    h[2] = __float2half(a.z); h[3] = __float2half(a.w);
                    h[4] = __float2half(b.x); h[5] = __float2half(b.y);
                    h[6] = __float2half(b.z); h[7] = __float2half(b.w);
                } else if (c < 28) {                // d2an region [128,224)
                    const float* dp = d2 + (size_t)n * PI_ + (k0 - ENC);
#pragma unroll
                    for (int q = 0; q < 4; q++) {
                        float2 f = *(const float2*)(dp + q * 2);
                        h[q * 2 + 0] = __float2half(f.x);
                        h[q * 2 + 1] = __float2half(f.y);
                    }
                } else if (c == 28) {               // [224,232): d2an idx 96,97 then zeros
                    float2 f = *(const float2*)(d2 + (size_t)n * PI_ + 96);
                    h[0] = __float2half(f.x);
                    h[1] = __float2half(f.y);
                }                                   // c == 29: zeros
            }
            *(uint4*)&As[r * SA + c * 8] = *(uint4*)h;
        }
    } else {
        for (int idx = tid; idx < totu4; idx += 256) {
            int r = idx / rowu4;
            int c = idx - r * rowu4;
            uint4 v = make_uint4(0, 0, 0, 0);
            if (bn + r < NN)
                v = *(const uint4*)(g_xmh + (size_t)(bn + r) * ENC + c * 8);
            *(uint4*)&As[r * SA + c * 8] = v;
        }
    }

    const int brow = tid >> 1;
    const int bcol = (tid & 1) * 8;
    const int bsoff = brow * 24 + bcol;

    const unsigned as_base = (unsigned)__cvta_generic_to_shared(As);
    const unsigned bs_base = (unsigned)__cvta_generic_to_shared(Bs);
    const unsigned a_off = ((wm * 64 + (lane & 15)) * SA + (lane >> 4) * 8) * 2;
    const unsigned b_off = ((wn * 32 + (lane & 7)) * 24 + ((lane >> 3) & 1) * 8) * 2;
    const unsigned BUFB = 128 * 24 * 2;

    for (int y = 0; y < 4; y++) {
        const __half* Bb = W + (size_t)(y * 128 + brow) * K + bcol;

        float c[4][4][4];
#pragma unroll
        for (int mi = 0; mi < 4; mi++)
#pragma unroll
            for (int ni = 0; ni < 4; ni++)
#pragma unroll
                for (int q = 0; q < 4; q++) c[mi][ni][q] = 0.0f;

        {
            uint4 bv0 = *(const uint4*)Bb;
            *(uint4*)&Bs[bsoff] = bv0;
        }
        __syncthreads();

        for (int ks = 0; ks < nk; ks++) {
            const int buf = ks & 1;
            uint4 bv = make_uint4(0, 0, 0, 0);
            const bool more = (ks + 1 < nk);
            if (more) bv = *(const uint4*)(Bb + (ks + 1) * 16);

            unsigned a[4][4], b[4][2];
#pragma unroll
            for (int mi = 0; mi < 4; mi++)
                ldsm4(a[mi][0], a[mi][1], a[mi][2], a[mi][3],
                      as_base + a_off + (unsigned)(mi * 16 * SA + ks * 16) * 2);
#pragma unroll
            for (int ni = 0; ni < 4; ni++)
                ldsm2(b[ni][0], b[ni][1],
                      bs_base + buf * BUFB + b_off + ni * 8 * 48);

#pragma unroll
            for (int mi = 0; mi < 4; mi++)
#pragma unroll
                for (int ni = 0; ni < 4; ni++)
                    mma16816(c[mi][ni][0], c[mi][ni][1], c[mi][ni][2], c[mi][ni][3],
                             a[mi][0], a[mi][1], a[mi][2], a[mi][3],
                             b[ni][0], b[ni][1]);

            if (more)
                *(uint4*)&Bs[(buf ^ 1) * (128 * 24) + bsoff] = bv;
            __syncthreads();
        }

#pragma unroll
        for (int mi = 0; mi < 4; mi++) {
            int row = bn + wm * 64 + mi * 16 + (lane >> 2);
#pragma unroll
            for (int ni = 0; ni < 4; ni++) {
                int colh2 = ((y * 128 + wn * 32 + ni * 8) >> 1) + (lane & 3);
                if (row < NN)
                    g_hh[(size_t)row * (MH / 2) + colh2] =
                        __floats2half2_rn(c[mi][ni][0], c[mi][ni][1]);
                if (row + 8 < NN)
                    g_hh[(size_t)(row + 8) * (MH / 2) + colh2] =
                        __floats2half2_rn(c[mi][ni][2], c[mi][ni][3]);
            }
        }
    }
}

// ---------------- fused aggregation: warp per node, uint4 gathers, unroll 8 ----------------
__global__ __launch_bounds__(256)
void k_agg(float* __restrict__ dst_ext, int use_ext) {
    int n = blockIdx.x * 8 + (threadIdx.x >> 5);
    if (n >= NN) return;
    int lane = threadIdx.x & 31;

    const uint4* hb = (const uint4*)g_hh;     // 64 uint4 per node row

    float s0 = g_dis[0][n]; s0 *= s0;
    float s1 = g_dis[1][n]; s1 *= s1;

    uint4 v0 = hb[(size_t)n * 64 + lane];
    uint4 v1 = hb[(size_t)n * 64 + 32 + lane];
    float2 a01 = __half22float2(*(__half2*)&v0.x), a23 = __half22float2(*(__half2*)&v0.y);
    float2 b01 = __half22float2(*(__half2*)&v0.z), b23 = __half22float2(*(__half2*)&v0.w);
    float2 c01 = __half22float2(*(__half2*)&v1.x), c23 = __half22float2(*(__half2*)&v1.y);
    float2 d01 = __half22float2(*(__half2*)&v1.z), d23 = __half22float2(*(__half2*)&v1.w);

    float acc0[4] = { fmaf(s0, a01.x, b01.x), fmaf(s0, a01.y, b01.y),
                      fmaf(s0, a23.x, b23.x), fmaf(s0, a23.y, b23.y) };
    float acc1[4] = { fmaf(s1, c01.x, d01.x), fmaf(s1, c01.y, d01.y),
                      fmaf(s1, c23.x, d23.x), fmaf(s1, c23.y, d23.y) };

    {
        int beg = g_rowptr[0][n], end = g_rowptr[0][n + 1];
#pragma unroll 8
        for (int j = beg; j < end; j++) {
            uint2 pk = __ldcs(&g_epk[0][j]);          // streamed, evict-first
            float2 de = __half22float2(*(__half2*)&pk.y);
            uint4 v = hb[(size_t)pk.x * 64 + lane];
            float2 fa0 = __half22float2(*(__half2*)&v.x);
            float2 fa1 = __half22float2(*(__half2*)&v.y);
            float2 fb0 = __half22float2(*(__half2*)&v.z);
            float2 fb1 = __half22float2(*(__half2*)&v.w);
            acc0[0] = fmaf(de.x, fa0.x, fmaf(de.y, fb0.x, acc0[0]));
            acc0[1] = fmaf(de.x, fa0.y, fmaf(de.y, fb0.y, acc0[1]));
            acc0[2] = fmaf(de.x, fa1.x, fmaf(de.y, fb1.x, acc0[2]));
            acc0[3] = fmaf(de.x, fa1.y, fmaf(de.y, fb1.y, acc0[3]));
        }
    }
    {
        int beg = g_rowptr[1][n], end = g_rowptr[1][n + 1];
#pragma unroll 8
        for (int j = beg; j < end; j++) {
            uint2 pk = __ldcs(&g_epk[1][j]);          // streamed, evict-first
            float2 de = __half22float2(*(__half2*)&pk.y);
            uint4 v = hb[(size_t)pk.x * 64 + 32 + lane];
            float2 fa0 = __half22float2(*(__half2*)&v.x);
            float2 fa1 = __half22float2(*(__half2*)&v.y);
            float2 fb0 = __half22float2(*(__half2*)&v.z);
            float2 fb1 = __half22float2(*(__half2*)&v.w);
            acc1[0] = fmaf(de.x, fa0.x, fmaf(de.y, fb0.x, acc1[0]));
            acc1[1] = fmaf(de.x, fa0.y, fmaf(de.y, fb0.y, acc1[1]));
            acc1[2] = fmaf(de.x, fa1.x, fmaf(de.y, fb1.x, acc1[2]));
            acc1[3] = fmaf(de.x, fa1.y, fmaf(de.y, fb1.y, acc1[3]));
        }
    }

    float4 o = make_float4(
        0.5f * (fmaxf(acc0[0], 0.f) + fmaxf(acc1[0], 0.f)),
        0.5f * (fmaxf(acc0[1], 0.f) + fmaxf(acc1[1], 0.f)),
        0.5f * (fmaxf(acc0[2], 0.f) + fmaxf(acc1[2], 0.f)),
        0.5f * (fmaxf(acc0[3], 0.f) + fmaxf(acc1[3], 0.f)));

    if (use_ext) {
        *(float4*)(dst_ext + (size_t)n * EMB + lane * 4) = o;
    } else {
        __half2 h0 = __floats2half2_rn(o.x, o.y);
        __half2 h1 = __floats2half2_rn(o.z, o.w);
        uint2 st;
        st.x = *(unsigned*)&h0;
        st.y = *(unsigned*)&h1;
        *(uint2*)(g_xmh + (size_t)n * ENC + lane * 4) = st;
    }
}

// ---------------- launch ----------------
extern "C" void kernel_launch(void* const* d_in, const int* in_sizes, int n_in,
                              void* d_out, int out_size) {
    const float* x    = (const float*)d_in[0];
    const float* d2an = (const float*)d_in[1];
    const int*   ei0  = (const int*)  d_in[2];
    const float* ew0  = (const float*)d_in[3];
    const int*   ei1  = (const int*)  d_in[4];
    const float* ew1  = (const float*)d_in[5];
    const float* nW1  = (const float*)d_in[6];
    const float* nW2  = (const float*)d_in[7];
    const float* W1a  = (const float*)d_in[8];
    const float* W1b  = (const float*)d_in[9];
    const float* W2a  = (const float*)d_in[10];
    const float* W2b  = (const float*)d_in[11];
    const float* W3a  = (const float*)d_in[12];
    const float* W3b  = (const float*)d_in[13];
    const float* W4a  = (const float*)d_in[14];
    const float* W4b  = (const float*)d_in[15];
    float* out = (float*)d_out;

    static cudaStream_t sideS = nullptr;
    static cudaEvent_t evF = nullptr, evJ = nullptr;
    if (sideS == nullptr) {
        cudaStreamCreateWithFlags(&sideS, cudaStreamNonBlocking);
        cudaEventCreateWithFlags(&evF, cudaEventDisableTiming);
        cudaEventCreateWithFlags(&evJ, cudaEventDisableTiming);
    }
    cudaFuncSetAttribute(k_gemm, cudaFuncAttributeMaxDynamicSharedMemorySize, 76800);

    const int TB = 256;
    const int ng = (NN + TB - 1) / TB;
    const int eg = (EE + TB - 1) / TB;

    // ---- fork: CSR build + stage-2 weights on side stream ----
    cudaEventRecord(evF, 0);
    cudaStreamWaitEvent(sideS, evF, 0);

    k_zero_cnt<<<ng, TB, 0, sideS>>>();
    k_hist    <<<eg, TB, 0, sideS>>>(ei0, ei1);
    k_scan1<<<dim3(NB_SCAN, 2), 1024, 0, sideS>>>();
    k_scan2<<<1, 64, 0, sideS>>>();
    k_scan3<<<dim3(ng, 2), TB, 0, sideS>>>();
    k_fill <<<dim3(eg, 2), TB, 0, sideS>>>(ei0, ew0, ei1, ew1);
    k_build_Wc2<<<(MH * ENC + TB - 1) / TB, TB, 0, sideS>>>(W3a, W3b, W4a, W4b);
    cudaEventRecord(evJ, sideS);

    // ---- main stream: stage-1 weights + gemm1 (concat fused into A-fill) ----
    k_build_Wc<<<(MH * KCH + TB - 1) / TB, TB>>>(W1a, W1b, W2a, W2b, nW1, nW2);

    const int gb = (NN + 127) / 128;
    const int ag = (NN + 7) / 8;
    const size_t smem1 = (size_t)(128 * (KCH + 8) + 2 * 128 * 24) * 2;  // 75,776 B
    const size_t smem2 = (size_t)(128 * (ENC + 8) + 2 * 128 * 24) * 2;  // 47,104 B

    k_gemm<<<gb, 256, smem1>>>(0, x, d2an);

    // ---- join: agg needs CSR + gemm1 ----
    cudaStreamWaitEvent(0, evJ, 0);
    k_agg<<<ag, 256>>>(nullptr, 0);        // -> g_xmh (fp16)

    // ---- stage 2 ----
    k_gemm<<<gb, 256, smem2>>>(1, nullptr, nullptr);
    k_agg <<<ag, 256>>>(out, 1);           // -> d_out
}

// round 14
// speedup vs baseline: 1.0685x; 1.0685x over previous
#include <cuda_runtime.h>
#include <cuda_fp16.h>
#include <cstdint>
#include <math.h>

#define NN   100000
#define EE   1600000
#define ENC  128
#define PI_  98
#define KIN  226          // ENC + PI
#define KCH  240          // KIN padded to multiple of 16
#define MH   512          // 4 stacked [*,128] outputs
#define EMB  128
#define NB_SCAN 98        // ceil(NN/1024)

// ---------------- scratch (static device globals; no allocation) ----------------
__device__ __half   g_wh1[MH * KCH];             // stage-1 fused weights fp16 (rows permuted)
__device__ __half   g_wh2[MH * ENC];             // stage-2 stacked weights fp16 (rows permuted)
__device__ __half   g_xmh[(size_t)NN * ENC];     // stage-1 result fp16
__device__ __align__(16) __half2 g_hh[(size_t)NN * (MH/2)];  // h, interleaved semantics

// CSR (per edge set)
__device__ int     g_cnt   [2][NN];
__device__ int     g_rowptr[2][NN + 1];
__device__ int     g_cur   [2][NN];
__device__ int     g_bsum  [2][NB_SCAN];
__device__ float   g_dis   [2][NN];
__device__ uint2   g_epk   [2][EE];              // {src, half2(dn,einv)}

// inverse interleave map, applied to weight ROWS (see round 10)
__device__ __forceinline__ int inv_feat(int f) {
    int c = f >> 1, t = f & 1;
    int s = c >> 7, q = c & 127;
    int i = ((q >> 2) << 1) | (q & 1);
    int p = (q >> 1) & 1;
    int cb = (s << 7) | (p << 6) | i;
    return (cb << 1) | t;
}

// ---------------- mma helpers ----------------
__device__ __forceinline__ void ldsm4(unsigned &r0, unsigned &r1, unsigned &r2, unsigned &r3,
                                      unsigned addr) {
    asm volatile("ldmatrix.sync.aligned.m8n8.x4.shared.b16 {%0,%1,%2,%3}, [%4];"
                 : "=r"(r0), "=r"(r1), "=r"(r2), "=r"(r3) : "r"(addr));
}
__device__ __forceinline__ void ldsm2(unsigned &r0, unsigned &r1, unsigned addr) {
    asm volatile("ldmatrix.sync.aligned.m8n8.x2.shared.b16 {%0,%1}, [%2];"
                 : "=r"(r0), "=r"(r1) : "r"(addr));
}
__device__ __forceinline__ void mma16816(float &c0, float &c1, float &c2, float &c3,
                                         unsigned a0, unsigned a1, unsigned a2, unsigned a3,
                                         unsigned b0, unsigned b1) {
    asm volatile("mma.sync.aligned.m16n8k16.row.col.f32.f16.f16.f32 "
                 "{%0,%1,%2,%3}, {%4,%5,%6,%7}, {%8,%9}, {%0,%1,%2,%3};"
                 : "+f"(c0), "+f"(c1), "+f"(c2), "+f"(c3)
                 : "r"(a0), "r"(a1), "r"(a2), "r"(a3), "r"(b0), "r"(b1));
}

// ---------------- CSR build ----------------
__global__ void k_zero_cnt() {
    int i = blockIdx.x * blockDim.x + threadIdx.x;
    if (i < NN) { g_cnt[0][i] = 0; g_cnt[1][i] = 0; }
}

__global__ void k_hist(const int* __restrict__ ei0, const int* __restrict__ ei1) {
    int e = blockIdx.x * blockDim.x + threadIdx.x;
    if (e < EE) {
        atomicAdd(&g_cnt[0][ei0[EE + e]], 1);
        atomicAdd(&g_cnt[1][ei1[EE + e]], 1);
    }
}

__global__ void k_scan1() {
    __shared__ int sh[1024];
    int which = blockIdx.y;
    int tid = threadIdx.x;
    int i = blockIdx.x * 1024 + tid;
    int v = (i < NN) ? g_cnt[which][i] : 0;
    sh[tid] = v; __syncthreads();
#pragma unroll
    for (int off = 1; off < 1024; off <<= 1) {
        int t = (tid >= off) ? sh[tid - off] : 0;
        __syncthreads();
        sh[tid] += t;
        __syncthreads();
    }
    if (i < NN) g_rowptr[which][i] = sh[tid] - v;     // exclusive
    if (tid == 1023) g_bsum[which][blockIdx.x] = sh[1023];
}

__global__ void k_scan2() {
    int which = threadIdx.x >> 5;
    if ((threadIdx.x & 31) == 0 && which < 2) {
        int s = 0;
        for (int i = 0; i < NB_SCAN; i++) { int t = g_bsum[which][i]; g_bsum[which][i] = s; s += t; }
    }
}

__global__ void k_scan3() {                           // + dis computation
    int which = blockIdx.y;
    int i = blockIdx.x * blockDim.x + threadIdx.x;
    if (i < NN) {
        int v = g_rowptr[which][i] + g_bsum[which][i >> 10];
        g_rowptr[which][i] = v;
        g_cur[which][i] = v;
        g_dis[which][i] = rsqrtf((float)(g_cnt[which][i] + 1));   // +1 self loop
    }
    if (i == 0) g_rowptr[which][NN] = EE;
}

__global__ void k_fill(const int* __restrict__ ei0, const float* __restrict__ ew0,
                       const int* __restrict__ ei1, const float* __restrict__ ew1) {
    int which = blockIdx.y;
    const int*   ei = which ? ei1 : ei0;
    const float* ew = which ? ew1 : ew0;
    int e = blockIdx.x * blockDim.x + threadIdx.x;
    if (e >= EE) return;
    int r = ei[e];
    int c = ei[EE + e];
    float w = ew[e];
    float dn   = g_dis[which][r] * g_dis[which][c];
    float einv = (w > 0.0f) ? fminf(rsqrtf(w), 1.0f) : 0.0f;
    int p = atomicAdd(&g_cur[which][c], 1);
    __half2 de = __floats2half2_rn(dn, einv);
    uint2 pk;
    pk.x = (unsigned)r;
    pk.y = *(unsigned*)&de;
    g_epk[which][p] = pk;
}

// ---------------- fused weights (rows permuted by inv_feat) ----------------
__global__ void k_build_Wc(const float* __restrict__ W1a, const float* __restrict__ W1b,
                           const float* __restrict__ W2a, const float* __restrict__ W2b,
                           const float* __restrict__ nW1, const float* __restrict__ nW2) {
    int i = blockIdx.x * blockDim.x + threadIdx.x;
    if (i >= MH * KCH) return;
    int m = i / KCH, k = i - m * KCH;
    int mo = inv_feat(m);
    float v = 0.0f;
    if (k < KIN) {
        const float* Ws = (mo < 128) ? W1a : (mo < 256) ? W1b : (mo < 384) ? W2a : W2b;
        const float* nW = (mo < 256) ? nW1 : nW2;
        int mm = mo & 127;
        float s = 0.0f;
#pragma unroll 8
        for (int j = 0; j < ENC; j++) s = fmaf(Ws[mm * ENC + j], nW[j * KIN + k], s);
        v = s;
    }
    g_wh1[i] = __float2half(v);
}

__global__ void k_build_Wc2(const float* __restrict__ W3a, const float* __restrict__ W3b,
                            const float* __restrict__ W4a, const float* __restrict__ W4b) {
    int i = blockIdx.x * blockDim.x + threadIdx.x;
    if (i >= MH * ENC) return;
    int m = i / ENC, k = i - m * ENC;
    int mo = inv_feat(m);
    const float* Ws = (mo < 128) ? W3a : (mo < 256) ? W3b : (mo < 384) ? W4a : W4b;
    g_wh2[i] = __float2half(Ws[(mo & 127) * ENC + k]);
}

// ---------------- persist-A tensor-core GEMM: C[N,512] = A[N,K] * W[512,K]^T ----------------
// stage 0: A = concat(x, d2an) built IN the fill (fp32 -> fp16 in flight)
// stage 1: A = g_xmh (fp16 direct)
__global__ __launch_bounds__(256, 2)
void k_gemm(int stage, const float* __restrict__ x, const float* __restrict__ d2) {
    extern __shared__ __align__(16) __half sm[];
    const __half* __restrict__ W = stage ? g_wh2 : g_wh1;
    const int K  = stage ? ENC : KCH;
    const int SA = K + 8;
    const int nk = K >> 4;

    __half* As = sm;                      // 128 x SA
    __half* Bs = sm + 128 * SA;           // 2 x 128 x 24

    const int tid  = threadIdx.x;
    const int lane = tid & 31;
    const int warp = tid >> 5;
    const int wm   = warp >> 2;
    const int wn   = warp & 3;
    const int bn   = blockIdx.x * 128;

    // ---- fill persistent A ----
    const int rowu4 = K >> 3;             // 30 (stage 0) or 16 (stage 1)
    const int totu4 = 128 * rowu4;
    if (stage == 0) {
        for (int idx = tid; idx < totu4; idx += 256) {
            int r = idx / rowu4;
            int c = idx - r * rowu4;
            int n = bn + r;
            __half h[8];
#pragma unroll
            for (int q = 0; q < 8; q++) h[q] = __float2half(0.0f);
            if (n < NN) {
                int k0 = c * 8;
                if (c < 16) {                       // x region [0,128)
                    float4 a = *(const float4*)(x + (size_t)n * ENC + k0);
                    float4 b = *(const float4*)(x + (size_t)n * ENC + k0 + 4);
                    h[0] = __float2half(a.x); h[1] = __float2half(a.y);
                    h[2] = __float2half(a.z); h[3] = __float2half(a.w);
                    h[4] = __float2half(b.x); h[5] = __float2half(b.y);
                    h[6] = __float2half(b.z); h[7] = __float2half(b.w);
                } else if (c < 28) {                // d2an region [128,224)
                    const float* dp = d2 + (size_t)n * PI_ + (k0 - ENC);
#pragma unroll
                    for (int q = 0; q < 4; q++) {
                        float2 f = *(const float2*)(dp + q * 2);
                        h[q * 2 + 0] = __float2half(f.x);
                        h[q * 2 + 1] = __float2half(f.y);
                    }
                } else if (c == 28) {               // [224,232): d2an idx 96,97 then zeros
                    float2 f = *(const float2*)(d2 + (size_t)n * PI_ + 96);
                    h[0] = __float2half(f.x);
                    h[1] = __float2half(f.y);
                }                                   // c == 29: zeros
            }
            *(uint4*)&As[r * SA + c * 8] = *(uint4*)h;
        }
    } else {
        for (int idx = tid; idx < totu4; idx += 256) {
            int r = idx / rowu4;
            int c = idx - r * rowu4;
            uint4 v = make_uint4(0, 0, 0, 0);
            if (bn + r < NN)
                v = *(const uint4*)(g_xmh + (size_t)(bn + r) * ENC + c * 8);
            *(uint4*)&As[r * SA + c * 8] = v;
        }
    }

    const int brow = tid >> 1;
    const int bcol = (tid & 1) * 8;
    const int bsoff = brow * 24 + bcol;

    const unsigned as_base = (unsigned)__cvta_generic_to_shared(As);
    const unsigned bs_base = (unsigned)__cvta_generic_to_shared(Bs);
    const unsigned a_off = ((wm * 64 + (lane & 15)) * SA + (lane >> 4) * 8) * 2;
    const unsigned b_off = ((wn * 32 + (lane & 7)) * 24 + ((lane >> 3) & 1) * 8) * 2;
    const unsigned BUFB = 128 * 24 * 2;

    for (int y = 0; y < 4; y++) {
        const __half* Bb = W + (size_t)(y * 128 + brow) * K + bcol;

        float c[4][4][4];
#pragma unroll
        for (int mi = 0; mi < 4; mi++)
#pragma unroll
            for (int ni = 0; ni < 4; ni++)
#pragma unroll
                for (int q = 0; q < 4; q++) c[mi][ni][q] = 0.0f;

        {
            uint4 bv0 = *(const uint4*)Bb;
            *(uint4*)&Bs[bsoff] = bv0;
        }
        __syncthreads();

        for (int ks = 0; ks < nk; ks++) {
            const int buf = ks & 1;
            uint4 bv = make_uint4(0, 0, 0, 0);
            const bool more = (ks + 1 < nk);
            if (more) bv = *(const uint4*)(Bb + (ks + 1) * 16);

            unsigned a[4][4], b[4][2];
#pragma unroll
            for (int mi = 0; mi < 4; mi++)
                ldsm4(a[mi][0], a[mi][1], a[mi][2], a[mi][3],
                      as_base + a_off + (unsigned)(mi * 16 * SA + ks * 16) * 2);
#pragma unroll
            for (int ni = 0; ni < 4; ni++)
                ldsm2(b[ni][0], b[ni][1],
                      bs_base + buf * BUFB + b_off + ni * 8 * 48);

#pragma unroll
            for (int mi = 0; mi < 4; mi++)
#pragma unroll
                for (int ni = 0; ni < 4; ni++)
                    mma16816(c[mi][ni][0], c[mi][ni][1], c[mi][ni][2], c[mi][ni][3],
                             a[mi][0], a[mi][1], a[mi][2], a[mi][3],
                             b[ni][0], b[ni][1]);

            if (more)
                *(uint4*)&Bs[(buf ^ 1) * (128 * 24) + bsoff] = bv;
            __syncthreads();
        }

#pragma unroll
        for (int mi = 0; mi < 4; mi++) {
            int row = bn + wm * 64 + mi * 16 + (lane >> 2);
#pragma unroll
            for (int ni = 0; ni < 4; ni++) {
                int colh2 = ((y * 128 + wn * 32 + ni * 8) >> 1) + (lane & 3);
                if (row < NN)
                    g_hh[(size_t)row * (MH / 2) + colh2] =
                        __floats2half2_rn(c[mi][ni][0], c[mi][ni][1]);
                if (row + 8 < NN)
                    g_hh[(size_t)(row + 8) * (MH / 2) + colh2] =
                        __floats2half2_rn(c[mi][ni][2], c[mi][ni][3]);
            }
        }
    }
}

// ---------------- fused aggregation: warp per node, uint4 gathers, unroll 8 ----------------
__global__ __launch_bounds__(256)
void k_agg(float* __restrict__ dst_ext, int use_ext) {
    int n = blockIdx.x * 8 + (threadIdx.x >> 5);
    if (n >= NN) return;
    int lane = threadIdx.x & 31;

    const uint4* hb = (const uint4*)g_hh;     // 64 uint4 per node row

    float s0 = g_dis[0][n]; s0 *= s0;
    float s1 = g_dis[1][n]; s1 *= s1;

    uint4 v0 = hb[(size_t)n * 64 + lane];
    uint4 v1 = hb[(size_t)n * 64 + 32 + lane];
    float2 a01 = __half22float2(*(__half2*)&v0.x), a23 = __half22float2(*(__half2*)&v0.y);
    float2 b01 = __half22float2(*(__half2*)&v0.z), b23 = __half22float2(*(__half2*)&v0.w);
    float2 c01 = __half22float2(*(__half2*)&v1.x), c23 = __half22float2(*(__half2*)&v1.y);
    float2 d01 = __half22float2(*(__half2*)&v1.z), d23 = __half22float2(*(__half2*)&v1.w);

    float acc0[4] = { fmaf(s0, a01.x, b01.x), fmaf(s0, a01.y, b01.y),
                      fmaf(s0, a23.x, b23.x), fmaf(s0, a23.y, b23.y) };
    float acc1[4] = { fmaf(s1, c01.x, d01.x), fmaf(s1, c01.y, d01.y),
                      fmaf(s1, c23.x, d23.x), fmaf(s1, c23.y, d23.y) };

    {
        int beg = g_rowptr[0][n], end = g_rowptr[0][n + 1];
#pragma unroll 8
        for (int j = beg; j < end; j++) {
            uint2 pk = g_epk[0][j];
            float2 de = __half22float2(*(__half2*)&pk.y);
            uint4 v = hb[(size_t)pk.x * 64 + lane];
            float2 fa0 = __half22float2(*(__half2*)&v.x);
            float2 fa1 = __half22float2(*(__half2*)&v.y);
            float2 fb0 = __half22float2(*(__half2*)&v.z);
            float2 fb1 = __half22float2(*(__half2*)&v.w);
            acc0[0] = fmaf(de.x, fa0.x, fmaf(de.y, fb0.x, acc0[0]));
            acc0[1] = fmaf(de.x, fa0.y, fmaf(de.y, fb0.y, acc0[1]));
            acc0[2] = fmaf(de.x, fa1.x, fmaf(de.y, fb1.x, acc0[2]));
            acc0[3] = fmaf(de.x, fa1.y, fmaf(de.y, fb1.y, acc0[3]));
        }
    }
    {
        int beg = g_rowptr[1][n], end = g_rowptr[1][n + 1];
#pragma unroll 8
        for (int j = beg; j < end; j++) {
            uint2 pk = g_epk[1][j];
            float2 de = __half22float2(*(__half2*)&pk.y);
            uint4 v = hb[(size_t)pk.x * 64 + 32 + lane];
            float2 fa0 = __half22float2(*(__half2*)&v.x);
            float2 fa1 = __half22float2(*(__half2*)&v.y);
            float2 fb0 = __half22float2(*(__half2*)&v.z);
            float2 fb1 = __half22float2(*(__half2*)&v.w);
            acc1[0] = fmaf(de.x, fa0.x, fmaf(de.y, fb0.x, acc1[0]));
            acc1[1] = fmaf(de.x, fa0.y, fmaf(de.y, fb0.y, acc1[1]));
            acc1[2] = fmaf(de.x, fa1.x, fmaf(de.y, fb1.x, acc1[2]));
            acc1[3] = fmaf(de.x, fa1.y, fmaf(de.y, fb1.y, acc1[3]));
        }
    }

    float4 o = make_float4(
        0.5f * (fmaxf(acc0[0], 0.f) + fmaxf(acc1[0], 0.f)),
        0.5f * (fmaxf(acc0[1], 0.f) + fmaxf(acc1[1], 0.f)),
        0.5f * (fmaxf(acc0[2], 0.f) + fmaxf(acc1[2], 0.f)),
        0.5f * (fmaxf(acc0[3], 0.f) + fmaxf(acc1[3], 0.f)));

    if (use_ext) {
        *(float4*)(dst_ext + (size_t)n * EMB + lane * 4) = o;
    } else {
        __half2 h0 = __floats2half2_rn(o.x, o.y);
        __half2 h1 = __floats2half2_rn(o.z, o.w);
        uint2 st;
        st.x = *(unsigned*)&h0;
        st.y = *(unsigned*)&h1;
        *(uint2*)(g_xmh + (size_t)n * ENC + lane * 4) = st;
    }
}

// ---------------- launch ----------------
extern "C" void kernel_launch(void* const* d_in, const int* in_sizes, int n_in,
                              void* d_out, int out_size) {
    const float* x    = (const float*)d_in[0];
    const float* d2an = (const float*)d_in[1];
    const int*   ei0  = (const int*)  d_in[2];
    const float* ew0  = (const float*)d_in[3];
    const int*   ei1  = (const int*)  d_in[4];
    const float* ew1  = (const float*)d_in[5];
    const float* nW1  = (const float*)d_in[6];
    const float* nW2  = (const float*)d_in[7];
    const float* W1a  = (const float*)d_in[8];
    const float* W1b  = (const float*)d_in[9];
    const float* W2a  = (const float*)d_in[10];
    const float* W2b  = (const float*)d_in[11];
    const float* W3a  = (const float*)d_in[12];
    const float* W3b  = (const float*)d_in[13];
    const float* W4a  = (const float*)d_in[14];
    const float* W4b  = (const float*)d_in[15];
    float* out = (float*)d_out;

    static cudaStream_t sideS = nullptr;
    static cudaEvent_t evF = nullptr, evJ = nullptr;
    if (sideS == nullptr) {
        cudaStreamCreateWithFlags(&sideS, cudaStreamNonBlocking);
        cudaEventCreateWithFlags(&evF, cudaEventDisableTiming);
        cudaEventCreateWithFlags(&evJ, cudaEventDisableTiming);
    }
    cudaFuncSetAttribute(k_gemm, cudaFuncAttributeMaxDynamicSharedMemorySize, 76800);

    const int TB = 256;
    const int ng = (NN + TB - 1) / TB;
    const int eg = (EE + TB - 1) / TB;

    // ---- fork: CSR build + stage-2 weights on side stream ----
    cudaEventRecord(evF, 0);
    cudaStreamWaitEvent(sideS, evF, 0);

    k_zero_cnt<<<ng, TB, 0, sideS>>>();
    k_hist    <<<eg, TB, 0, sideS>>>(ei0, ei1);
    k_scan1<<<dim3(NB_SCAN, 2), 1024, 0, sideS>>>();
    k_scan2<<<1, 64, 0, sideS>>>();
    k_scan3<<<dim3(ng, 2), TB, 0, sideS>>>();
    k_fill <<<dim3(eg, 2), TB, 0, sideS>>>(ei0, ew0, ei1, ew1);
    k_build_Wc2<<<(MH * ENC + TB - 1) / TB, TB, 0, sideS>>>(W3a, W3b, W4a, W4b);
    cudaEventRecord(evJ, sideS);

    // ---- main stream: stage-1 weights + gemm1 (concat fused into A-fill) ----
    k_build_Wc<<<(MH * KCH + TB - 1) / TB, TB>>>(W1a, W1b, W2a, W2b, nW1, nW2);

    const int gb = (NN + 127) / 128;
    const int ag = (NN + 7) / 8;
    const size_t smem1 = (size_t)(128 * (KCH + 8) + 2 * 128 * 24) * 2;  // 75,776 B
    const size_t smem2 = (size_t)(128 * (ENC + 8) + 2 * 128 * 24) * 2;  // 47,104 B

    k_gemm<<<gb, 256, smem1>>>(0, x, d2an);

    // ---- join: agg needs CSR + gemm1 ----
    cudaStreamWaitEvent(0, evJ, 0);
    k_agg<<<ag, 256>>>(nullptr, 0);        // -> g_xmh (fp16)

    // ---- stage 2 ----
    k_gemm<<<gb, 256, smem2>>>(1, nullptr, nullptr);
    k_agg <<<ag, 256>>>(out, 1);           // -> d_out
}

// round 15
// speedup vs baseline: 1.1158x; 1.0444x over previous
#include <cuda_runtime.h>
#include <cuda_fp16.h>
#include <cstdint>
#include <math.h>

#define NN   100000
#define EE   1600000
#define ENC  128
#define PI_  98
#define KIN  226          // ENC + PI
#define KCH  240          // KIN padded to multiple of 16
#define MH   512          // 4 stacked [*,128] outputs
#define EMB  128
#define NB_SCAN 98        // ceil(NN/1024)

// ---------------- scratch (static device globals; no allocation) ----------------
__device__ __half   g_wh1[MH * KCH];             // stage-1 fused weights fp16 (rows permuted)
__device__ __half   g_wh2[MH * ENC];             // stage-2 stacked weights fp16 (rows permuted)
__device__ __half   g_xmh[(size_t)NN * ENC];     // stage-1 result fp16
__device__ __half   g_t  [(size_t)NN * ENC];     // per-stage partial: 0.5*relu(acc_set0)
__device__ __align__(16) __half2 g_hh[(size_t)NN * (MH/2)];  // h, interleaved semantics

// CSR (per edge set)
__device__ int     g_cnt   [2][NN];
__device__ int     g_rowptr[2][NN + 1];
__device__ int     g_cur   [2][NN];
__device__ int     g_bsum  [2][NB_SCAN];
__device__ float   g_dis   [2][NN];
__device__ uint2   g_epk   [2][EE];              // {src, half2(dn,einv)}

// inverse interleave map, applied to weight ROWS (see round 10)
__device__ __forceinline__ int inv_feat(int f) {
    int c = f >> 1, t = f & 1;
    int s = c >> 7, q = c & 127;
    int i = ((q >> 2) << 1) | (q & 1);
    int p = (q >> 1) & 1;
    int cb = (s << 7) | (p << 6) | i;
    return (cb << 1) | t;
}

// ---------------- mma helpers ----------------
__device__ __forceinline__ void ldsm4(unsigned &r0, unsigned &r1, unsigned &r2, unsigned &r3,
                                      unsigned addr) {
    asm volatile("ldmatrix.sync.aligned.m8n8.x4.shared.b16 {%0,%1,%2,%3}, [%4];"
                 : "=r"(r0), "=r"(r1), "=r"(r2), "=r"(r3) : "r"(addr));
}
__device__ __forceinline__ void ldsm2(unsigned &r0, unsigned &r1, unsigned addr) {
    asm volatile("ldmatrix.sync.aligned.m8n8.x2.shared.b16 {%0,%1}, [%2];"
                 : "=r"(r0), "=r"(r1) : "r"(addr));
}
__device__ __forceinline__ void mma16816(float &c0, float &c1, float &c2, float &c3,
                                         unsigned a0, unsigned a1, unsigned a2, unsigned a3,
                                         unsigned b0, unsigned b1) {
    asm volatile("mma.sync.aligned.m16n8k16.row.col.f32.f16.f16.f32 "
                 "{%0,%1,%2,%3}, {%4,%5,%6,%7}, {%8,%9}, {%0,%1,%2,%3};"
                 : "+f"(c0), "+f"(c1), "+f"(c2), "+f"(c3)
                 : "r"(a0), "r"(a1), "r"(a2), "r"(a3), "r"(b0), "r"(b1));
}

// ---------------- CSR build ----------------
__global__ void k_zero_cnt() {
    int i = blockIdx.x * blockDim.x + threadIdx.x;
    if (i < NN) { g_cnt[0][i] = 0; g_cnt[1][i] = 0; }
}

__global__ void k_hist(const int* __restrict__ ei0, const int* __restrict__ ei1) {
    int e = blockIdx.x * blockDim.x + threadIdx.x;
    if (e < EE) {
        atomicAdd(&g_cnt[0][ei0[EE + e]], 1);
        atomicAdd(&g_cnt[1][ei1[EE + e]], 1);
    }
}

__global__ void k_scan1() {
    __shared__ int sh[1024];
    int which = blockIdx.y;
    int tid = threadIdx.x;
    int i = blockIdx.x * 1024 + tid;
    int v = (i < NN) ? g_cnt[which][i] : 0;
    sh[tid] = v; __syncthreads();
#pragma unroll
    for (int off = 1; off < 1024; off <<= 1) {
        int t = (tid >= off) ? sh[tid - off] : 0;
        __syncthreads();
        sh[tid] += t;
        __syncthreads();
    }
    if (i < NN) g_rowptr[which][i] = sh[tid] - v;     // exclusive
    if (tid == 1023) g_bsum[which][blockIdx.x] = sh[1023];
}

__global__ void k_scan2() {
    int which = threadIdx.x >> 5;
    if ((threadIdx.x & 31) == 0 && which < 2) {
        int s = 0;
        for (int i = 0; i < NB_SCAN; i++) { int t = g_bsum[which][i]; g_bsum[which][i] = s; s += t; }
    }
}

__global__ void k_scan3() {                           // + dis computation
    int which = blockIdx.y;
    int i = blockIdx.x * blockDim.x + threadIdx.x;
    if (i < NN) {
        int v = g_rowptr[which][i] + g_bsum[which][i >> 10];
        g_rowptr[which][i] = v;
        g_cur[which][i] = v;
        g_dis[which][i] = rsqrtf((float)(g_cnt[which][i] + 1));   // +1 self loop
    }
    if (i == 0) g_rowptr[which][NN] = EE;
}

__global__ void k_fill(const int* __restrict__ ei0, const float* __restrict__ ew0,
                       const int* __restrict__ ei1, const float* __restrict__ ew1) {
    int which = blockIdx.y;
    const int*   ei = which ? ei1 : ei0;
    const float* ew = which ? ew1 : ew0;
    int e = blockIdx.x * blockDim.x + threadIdx.x;
    if (e >= EE) return;
    int r = ei[e];
    int c = ei[EE + e];
    float w = ew[e];
    float dn   = g_dis[which][r] * g_dis[which][c];
    float einv = (w > 0.0f) ? fminf(rsqrtf(w), 1.0f) : 0.0f;
    int p = atomicAdd(&g_cur[which][c], 1);
    __half2 de = __floats2half2_rn(dn, einv);
    uint2 pk;
    pk.x = (unsigned)r;
    pk.y = *(unsigned*)&de;
    g_epk[which][p] = pk;
}

// ---------------- fused weights (rows permuted by inv_feat) ----------------
__global__ void k_build_Wc(const float* __restrict__ W1a, const float* __restrict__ W1b,
                           const float* __restrict__ W2a, const float* __restrict__ W2b,
                           const float* __restrict__ nW1, const float* __restrict__ nW2) {
    int i = blockIdx.x * blockDim.x + threadIdx.x;
    if (i >= MH * KCH) return;
    int m = i / KCH, k = i - m * KCH;
    int mo = inv_feat(m);
    float v = 0.0f;
    if (k < KIN) {
        const float* Ws = (mo < 128) ? W1a : (mo < 256) ? W1b : (mo < 384) ? W2a : W2b;
        const float* nW = (mo < 256) ? nW1 : nW2;
        int mm = mo & 127;
        float s = 0.0f;
#pragma unroll 8
        for (int j = 0; j < ENC; j++) s = fmaf(Ws[mm * ENC + j], nW[j * KIN + k], s);
        v = s;
    }
    g_wh1[i] = __float2half(v);
}

__global__ void k_build_Wc2(const float* __restrict__ W3a, const float* __restrict__ W3b,
                            const float* __restrict__ W4a, const float* __restrict__ W4b) {
    int i = blockIdx.x * blockDim.x + threadIdx.x;
    if (i >= MH * ENC) return;
    int m = i / ENC, k = i - m * ENC;
    int mo = inv_feat(m);
    const float* Ws = (mo < 128) ? W3a : (mo < 256) ? W3b : (mo < 384) ? W4a : W4b;
    g_wh2[i] = __float2half(Ws[(mo & 127) * ENC + k]);
}

// ---------------- persist-A tensor-core GEMM: C[N,512] = A[N,K] * W[512,K]^T ----------------
// stage 0: A = concat(x, d2an) built IN the fill (fp32 -> fp16 in flight)
// stage 1: A = g_xmh (fp16 direct)
__global__ __launch_bounds__(256, 2)
void k_gemm(int stage, const float* __restrict__ x, const float* __restrict__ d2) {
    extern __shared__ __align__(16) __half sm[];
    const __half* __restrict__ W = stage ? g_wh2 : g_wh1;
    const int K  = stage ? ENC : KCH;
    const int SA = K + 8;
    const int nk = K >> 4;

    __half* As = sm;                      // 128 x SA
    __half* Bs = sm + 128 * SA;           // 2 x 128 x 24

    const int tid  = threadIdx.x;
    const int lane = tid & 31;
    const int warp = tid >> 5;
    const int wm   = warp >> 2;
    const int wn   = warp & 3;
    const int bn   = blockIdx.x * 128;

    // ---- fill persistent A ----
    const int rowu4 = K >> 3;             // 30 (stage 0) or 16 (stage 1)
    const int totu4 = 128 * rowu4;
    if (stage == 0) {
        for (int idx = tid; idx < totu4; idx += 256) {
            int r = idx / rowu4;
            int c = idx - r * rowu4;
            int n = bn + r;
            __half h[8];
#pragma unroll
            for (int q = 0; q < 8; q++) h[q] = __float2half(0.0f);
            if (n < NN) {
                int k0 = c * 8;
                if (c < 16) {                       // x region [0,128)
                    float4 a = *(const float4*)(x + (size_t)n * ENC + k0);
                    float4 b = *(const float4*)(x + (size_t)n * ENC + k0 + 4);
                    h[0] = __float2half(a.x); h[1] = __float2half(a.y);
                    h[2] = __float2half(a.z); h[3] = __float2half(a.w);
                    h[4] = __float2half(b.x); h[5] = __float2half(b.y);
                    h[6] = __float2half(b.z); h[7] = __float2half(b.w);
                } else if (c < 28) {                // d2an region [128,224)
                    const float* dp = d2 + (size_t)n * PI_ + (k0 - ENC);
#pragma unroll
                    for (int q = 0; q < 4; q++) {
                        float2 f = *(const float2*)(dp + q * 2);
                        h[q * 2 + 0] = __float2half(f.x);
                        h[q * 2 + 1] = __float2half(f.y);
                    }
                } else if (c == 28) {               // [224,232): d2an idx 96,97 then zeros
                    float2 f = *(const float2*)(d2 + (size_t)n * PI_ + 96);
                    h[0] = __float2half(f.x);
                    h[1] = __float2half(f.y);
                }                                   // c == 29: zeros
            }
            *(uint4*)&As[r * SA + c * 8] = *(uint4*)h;
        }
    } else {
        for (int idx = tid; idx < totu4; idx += 256) {
            int r = idx / rowu4;
            int c = idx - r * rowu4;
            uint4 v = make_uint4(0, 0, 0, 0);
            if (bn + r < NN)
                v = *(const uint4*)(g_xmh + (size_t)(bn + r) * ENC + c * 8);
            *(uint4*)&As[r * SA + c * 8] = v;
        }
    }

    const int brow = tid >> 1;
    const int bcol = (tid & 1) * 8;
    const int bsoff = brow * 24 + bcol;

    const unsigned as_base = (unsigned)__cvta_generic_to_shared(As);
    const unsigned bs_base = (unsigned)__cvta_generic_to_shared(Bs);
    const unsigned a_off = ((wm * 64 + (lane & 15)) * SA + (lane >> 4) * 8) * 2;
    const unsigned b_off = ((wn * 32 + (lane & 7)) * 24 + ((lane >> 3) & 1) * 8) * 2;
    const unsigned BUFB = 128 * 24 * 2;

    for (int y = 0; y < 4; y++) {
        const __half* Bb = W + (size_t)(y * 128 + brow) * K + bcol;

        float c[4][4][4];
#pragma unroll
        for (int mi = 0; mi < 4; mi++)
#pragma unroll
            for (int ni = 0; ni < 4; ni++)
#pragma unroll
                for (int q = 0; q < 4; q++) c[mi][ni][q] = 0.0f;

        {
            uint4 bv0 = *(const uint4*)Bb;
            *(uint4*)&Bs[bsoff] = bv0;
        }
        __syncthreads();

        for (int ks = 0; ks < nk; ks++) {
            const int buf = ks & 1;
            uint4 bv = make_uint4(0, 0, 0, 0);
            const bool more = (ks + 1 < nk);
            if (more) bv = *(const uint4*)(Bb + (ks + 1) * 16);

            unsigned a[4][4], b[4][2];
#pragma unroll
            for (int mi = 0; mi < 4; mi++)
                ldsm4(a[mi][0], a[mi][1], a[mi][2], a[mi][3],
                      as_base + a_off + (unsigned)(mi * 16 * SA + ks * 16) * 2);
#pragma unroll
            for (int ni = 0; ni < 4; ni++)
                ldsm2(b[ni][0], b[ni][1],
                      bs_base + buf * BUFB + b_off + ni * 8 * 48);

#pragma unroll
            for (int mi = 0; mi < 4; mi++)
#pragma unroll
                for (int ni = 0; ni < 4; ni++)
                    mma16816(c[mi][ni][0], c[mi][ni][1], c[mi][ni][2], c[mi][ni][3],
                             a[mi][0], a[mi][1], a[mi][2], a[mi][3],
                             b[ni][0], b[ni][1]);

            if (more)
                *(uint4*)&Bs[(buf ^ 1) * (128 * 24) + bsoff] = bv;
            __syncthreads();
        }

#pragma unroll
        for (int mi = 0; mi < 4; mi++) {
            int row = bn + wm * 64 + mi * 16 + (lane >> 2);
#pragma unroll
            for (int ni = 0; ni < 4; ni++) {
                int colh2 = ((y * 128 + wn * 32 + ni * 8) >> 1) + (lane & 3);
                if (row < NN)
                    g_hh[(size_t)row * (MH / 2) + colh2] =
                        __floats2half2_rn(c[mi][ni][0], c[mi][ni][1]);
                if (row + 8 < NN)
                    g_hh[(size_t)(row + 8) * (MH / 2) + colh2] =
                        __floats2half2_rn(c[mi][ni][2], c[mi][ni][3]);
            }
        }
    }
}

// ---------------- per-set aggregation: warp per node, uint4 gathers, unroll 8 ----------------
// mode 0: g_t = 0.5*relu(acc)                (set-0 pass)
// mode 1: g_xmh = g_t + 0.5*relu(acc)  fp16  (stage-1 finalize)
// mode 2: dst   = g_t + 0.5*relu(acc)  fp32  (stage-2 finalize)
__global__ __launch_bounds__(256)
void k_aggs(int ws, int mode, float* __restrict__ dst_ext) {
    int n = blockIdx.x * 8 + (threadIdx.x >> 5);
    if (n >= NN) return;
    int lane = threadIdx.x & 31;

    const uint4* hb = (const uint4*)g_hh;     // 64 uint4 per node row; set s at +s*32

    float s = g_dis[ws][n]; s *= s;

    uint4 v0 = hb[(size_t)n * 64 + ws * 32 + lane];
    float2 a01 = __half22float2(*(__half2*)&v0.x), a23 = __half22float2(*(__half2*)&v0.y);
    float2 b01 = __half22float2(*(__half2*)&v0.z), b23 = __half22float2(*(__half2*)&v0.w);

    float acc[4] = { fmaf(s, a01.x, b01.x), fmaf(s, a01.y, b01.y),
                     fmaf(s, a23.x, b23.x), fmaf(s, a23.y, b23.y) };

    {
        int beg = g_rowptr[ws][n], end = g_rowptr[ws][n + 1];
#pragma unroll 8
        for (int j = beg; j < end; j++) {
            uint2 pk = g_epk[ws][j];
            float2 de = __half22float2(*(__half2*)&pk.y);
            uint4 v = hb[(size_t)pk.x * 64 + ws * 32 + lane];
            float2 fa0 = __half22float2(*(__half2*)&v.x);
            float2 fa1 = __half22float2(*(__half2*)&v.y);
            float2 fb0 = __half22float2(*(__half2*)&v.z);
            float2 fb1 = __half22float2(*(__half2*)&v.w);
            acc[0] = fmaf(de.x, fa0.x, fmaf(de.y, fb0.x, acc[0]));
            acc[1] = fmaf(de.x, fa0.y, fmaf(de.y, fb0.y, acc[1]));
            acc[2] = fmaf(de.x, fa1.x, fmaf(de.y, fb1.x, acc[2]));
            acc[3] = fmaf(de.x, fa1.y, fmaf(de.y, fb1.y, acc[3]));
        }
    }

    float r0 = 0.5f * fmaxf(acc[0], 0.f);
    float r1 = 0.5f * fmaxf(acc[1], 0.f);
    float r2 = 0.5f * fmaxf(acc[2], 0.f);
    float r3 = 0.5f * fmaxf(acc[3], 0.f);

    if (mode == 0) {
        __half2 h0 = __floats2half2_rn(r0, r1);
        __half2 h1 = __floats2half2_rn(r2, r3);
        uint2 st;
        st.x = *(unsigned*)&h0;
        st.y = *(unsigned*)&h1;
        *(uint2*)(g_t + (size_t)n * ENC + lane * 4) = st;
    } else {
        uint2 tv = *(const uint2*)(g_t + (size_t)n * ENC + lane * 4);
        float2 t01 = __half22float2(*(__half2*)&tv.x);
        float2 t23 = __half22float2(*(__half2*)&tv.y);
        float o0 = t01.x + r0, o1 = t01.y + r1;
        float o2 = t23.x + r2, o3 = t23.y + r3;
        if (mode == 1) {
            __half2 h0 = __floats2half2_rn(o0, o1);
            __half2 h1 = __floats2half2_rn(o2, o3);
            uint2 st;
            st.x = *(unsigned*)&h0;
            st.y = *(unsigned*)&h1;
            *(uint2*)(g_xmh + (size_t)n * ENC + lane * 4) = st;
        } else {
            *(float4*)(dst_ext + (size_t)n * EMB + lane * 4) = make_float4(o0, o1, o2, o3);
        }
    }
}

// ---------------- launch ----------------
extern "C" void kernel_launch(void* const* d_in, const int* in_sizes, int n_in,
                              void* d_out, int out_size) {
    const float* x    = (const float*)d_in[0];
    const float* d2an = (const float*)d_in[1];
    const int*   ei0  = (const int*)  d_in[2];
    const float* ew0  = (const float*)d_in[3];
    const int*   ei1  = (const int*)  d_in[4];
    const float* ew1  = (const float*)d_in[5];
    const float* nW1  = (const float*)d_in[6];
    const float* nW2  = (const float*)d_in[7];
    const float* W1a  = (const float*)d_in[8];
    const float* W1b  = (const float*)d_in[9];
    const float* W2a  = (const float*)d_in[10];
    const float* W2b  = (const float*)d_in[11];
    const float* W3a  = (const float*)d_in[12];
    const float* W3b  = (const float*)d_in[13];
    const float* W4a  = (const float*)d_in[14];
    const float* W4b  = (const float*)d_in[15];
    float* out = (float*)d_out;

    static cudaStream_t sideS = nullptr;
    static cudaEvent_t evF = nullptr, evJ = nullptr;
    if (sideS == nullptr) {
        cudaStreamCreateWithFlags(&sideS, cudaStreamNonBlocking);
        cudaEventCreateWithFlags(&evF, cudaEventDisableTiming);
        cudaEventCreateWithFlags(&evJ, cudaEventDisableTiming);
    }
    cudaFuncSetAttribute(k_gemm, cudaFuncAttributeMaxDynamicSharedMemorySize, 76800);

    const int TB = 256;
    const int ng = (NN + TB - 1) / TB;
    const int eg = (EE + TB - 1) / TB;

    // ---- fork: CSR build + stage-2 weights on side stream ----
    cudaEventRecord(evF, 0);
    cudaStreamWaitEvent(sideS, evF, 0);

    k_zero_cnt<<<ng, TB, 0, sideS>>>();
    k_hist    <<<eg, TB, 0, sideS>>>(ei0, ei1);
    k_scan1<<<dim3(NB_SCAN, 2), 1024, 0, sideS>>>();
    k_scan2<<<1, 64, 0, sideS>>>();
    k_scan3<<<dim3(ng, 2), TB, 0, sideS>>>();
    k_fill <<<dim3(eg, 2), TB, 0, sideS>>>(ei0, ew0, ei1, ew1);
    k_build_Wc2<<<(MH * ENC + TB - 1) / TB, TB, 0, sideS>>>(W3a, W3b, W4a, W4b);
    cudaEventRecord(evJ, sideS);

    // ---- main stream: stage-1 weights + gemm1 (concat fused into A-fill) ----
    k_build_Wc<<<(MH * KCH + TB - 1) / TB, TB>>>(W1a, W1b, W2a, W2b, nW1, nW2);

    const int gb = (NN + 127) / 128;
    const int ag = (NN + 7) / 8;
    const size_t smem1 = (size_t)(128 * (KCH + 8) + 2 * 128 * 24) * 2;  // 75,776 B
    const size_t smem2 = (size_t)(128 * (ENC + 8) + 2 * 128 * 24) * 2;  // 47,104 B

    k_gemm<<<gb, 256, smem1>>>(0, x, d2an);

    // ---- join: agg needs CSR + gemm1 ----
    cudaStreamWaitEvent(0, evJ, 0);

    // ---- stage-1 aggregation: two L2-resident passes ----
    k_aggs<<<ag, 256>>>(0, 0, nullptr);    // set 0 -> g_t
    k_aggs<<<ag, 256>>>(1, 1, nullptr);    // set 1 + g_t -> g_xmh

    // ---- stage 2 ----
    k_gemm<<<gb, 256, smem2>>>(1, nullptr, nullptr);
    k_aggs<<<ag, 256>>>(0, 0, nullptr);    // set 0 -> g_t
    k_aggs<<<ag, 256>>>(1, 2, out);        // set 1 + g_t -> d_out
}